// round 2
// baseline (speedup 1.0000x reference)
#include <cuda_runtime.h>
#include <math.h>

// Problem constants
#define BB 4
#define SS 8192
#define HH 768
#define NH 12
#define HD 64
#define MM 64
#define NTOK (BB * SS)          // 32768
#define BHS (BB * NH)           // 48
#define EPSF 1e-6f

// ---------------- scratch (device globals; no allocation allowed) ----------------
__device__ float g_q[(size_t)NTOK * HH];
__device__ float g_k[(size_t)NTOK * HH];
__device__ float g_v[(size_t)NTOK * HH];
__device__ float g_qp[(size_t)BHS * SS * MM];
__device__ float g_kp[(size_t)BHS * SS * MM];
__device__ float g_kv[(size_t)BHS * MM * HD];
__device__ float g_ksum[(size_t)BHS * MM];
__device__ float g_ctx[(size_t)NTOK * HH];

// ---------------- GEMM: C[M,N] = A[M,K] @ W[K,N] + bias[N] ----------------
// BM=64, BN=64, BK=16, 256 threads, 4x4 microtile per thread.
__global__ void gemm_bias_kernel(const float* __restrict__ A,
                                 const float* __restrict__ W,
                                 const float* __restrict__ bias,
                                 float* __restrict__ C,
                                 int Mrows, int K, int Ncols) {
    const int BM = 64, BN = 64, BK = 16;
    __shared__ float As[BK][BM + 1];
    __shared__ float Ws[BK][BN + 1];

    int tid = threadIdx.x;          // 0..255
    int tx = tid % 16;              // N direction
    int ty = tid / 16;              // M direction
    int row0 = blockIdx.y * BM;
    int col0 = blockIdx.x * BN;

    float acc[4][4] = {};

    for (int k0 = 0; k0 < K; k0 += BK) {
        // A tile: 64x16 = 1024 elems, 4 per thread
        #pragma unroll
        for (int i = 0; i < 4; i++) {
            int idx = tid + i * 256;
            int r = idx / BK, c = idx % BK;
            As[c][r] = A[(size_t)(row0 + r) * K + (k0 + c)];
        }
        // W tile: 16x64 = 1024 elems
        #pragma unroll
        for (int i = 0; i < 4; i++) {
            int idx = tid + i * 256;
            int r = idx / BN, c = idx % BN;
            Ws[r][c] = W[(size_t)(k0 + r) * Ncols + (col0 + c)];
        }
        __syncthreads();

        #pragma unroll
        for (int k = 0; k < BK; k++) {
            float a[4], b[4];
            #pragma unroll
            for (int i = 0; i < 4; i++) a[i] = As[k][ty * 4 + i];
            #pragma unroll
            for (int j = 0; j < 4; j++) b[j] = Ws[k][tx * 4 + j];
            #pragma unroll
            for (int i = 0; i < 4; i++)
                #pragma unroll
                for (int j = 0; j < 4; j++)
                    acc[i][j] = fmaf(a[i], b[j], acc[i][j]);
        }
        __syncthreads();
    }

    #pragma unroll
    for (int i = 0; i < 4; i++) {
        int r = row0 + ty * 4 + i;
        #pragma unroll
        for (int j = 0; j < 4; j++) {
            int c = col0 + tx * 4 + j;
            C[(size_t)r * Ncols + c] = acc[i][j] + bias[c];
        }
    }
}

// ---------------- random-feature projection + stabilized exp ----------------
// grid: (SS/64, BHS), block: 64 threads. Each block: load P[h] (64x64) once,
// then process 64 sequence rows.
__global__ void proj_exp_kernel(const float* __restrict__ qk,     // [NTOK, HH]
                                const float* __restrict__ P,      // [NH, HD, MM]
                                float* __restrict__ outp) {       // [BHS, SS, MM]
    int bh = blockIdx.y;
    int b = bh / NH, h = bh % NH;
    int tid = threadIdx.x;          // m index, 0..63

    __shared__ float Ps[HD][MM + 1];
    __shared__ float row[HD];
    __shared__ float vals[MM];

    for (int i = tid; i < HD * MM; i += 64)
        Ps[i / MM][i % MM] = P[(size_t)h * HD * MM + i];
    __syncthreads();

    int s0 = blockIdx.x * 64;
    for (int r = 0; r < 64; r++) {
        int s = s0 + r;
        row[tid] = qk[((size_t)(b * SS + s)) * HH + h * HD + tid];
        __syncthreads();

        float acc = 0.f;
        #pragma unroll
        for (int d = 0; d < HD; d++)
            acc = fmaf(row[d], Ps[d][tid], acc);

        vals[tid] = acc;
        __syncthreads();
        // max-reduce over 64 values
        #pragma unroll
        for (int off = 32; off > 0; off >>= 1) {
            if (tid < off) vals[tid] = fmaxf(vals[tid], vals[tid + off]);
            __syncthreads();
        }
        float mx = vals[0];
        __syncthreads();

        outp[((size_t)bh * SS + s) * MM + tid] = __expf(acc - mx);
        __syncthreads();
    }
}

// ---------------- zero kv scratch ----------------
__global__ void zero_kernel(float* __restrict__ p, int n) {
    int i = blockIdx.x * blockDim.x + threadIdx.x;
    if (i < n) p[i] = 0.f;
}

// ---------------- kv = sum_n kp[n,m] * v[n,d]; ksum = sum_n kp[n,m] ----------------
// grid: (SPLITS=64, BHS), block: 256. Each thread owns (m = tid%64, 16 d's).
__global__ void kv_accum_kernel(const float* __restrict__ kp,   // [BHS, SS, MM]
                                const float* __restrict__ v,    // [NTOK, HH]
                                float* __restrict__ kv,         // [BHS, MM, HD]
                                float* __restrict__ ksum) {     // [BHS, MM]
    const int SPLITS = 64;
    const int ROWS = SS / SPLITS;   // 128
    const int CH = 16;

    int bh = blockIdx.y;
    int b = bh / NH, h = bh % NH;
    int split = blockIdx.x;
    int tid = threadIdx.x;
    int m = tid % 64;
    int dg = tid / 64;              // 0..3, owns d in [dg*16, dg*16+16)

    __shared__ float kps[CH][MM];
    __shared__ float vs[CH][HD];

    float acc[16] = {};
    float ks = 0.f;

    int n0 = split * ROWS;
    for (int c0 = 0; c0 < ROWS; c0 += CH) {
        for (int i = tid; i < CH * 64; i += 256) {
            int r = i / 64, cc = i % 64;
            int n = n0 + c0 + r;
            kps[r][cc] = kp[((size_t)bh * SS + n) * MM + cc];
            vs[r][cc]  = v[((size_t)(b * SS + n)) * HH + h * HD + cc];
        }
        __syncthreads();
        #pragma unroll
        for (int r = 0; r < CH; r++) {
            float a = kps[r][m];
            if (dg == 0) ks += a;
            #pragma unroll
            for (int j = 0; j < 16; j++)
                acc[j] = fmaf(a, vs[r][dg * 16 + j], acc[j]);
        }
        __syncthreads();
    }

    float* kvp = kv + ((size_t)bh * MM + m) * HD + dg * 16;
    #pragma unroll
    for (int j = 0; j < 16; j++) atomicAdd(&kvp[j], acc[j]);
    if (dg == 0) atomicAdd(&ksum[(size_t)bh * MM + m], ks);
}

// ---------------- ctx = (qp @ kv) / (qp @ ksum + eps) ----------------
// grid: (SS/64, BHS), block: 64 (thread = d index)
__global__ void qkv_norm_kernel(const float* __restrict__ qp,    // [BHS, SS, MM]
                                const float* __restrict__ kv,    // [BHS, MM, HD]
                                const float* __restrict__ ksum,  // [BHS, MM]
                                float* __restrict__ ctx) {       // [NTOK, HH]
    int bh = blockIdx.y;
    int b = bh / NH, h = bh % NH;
    int tid = threadIdx.x;          // d

    __shared__ float kvs[MM][HD + 1];
    __shared__ float kss[MM];
    __shared__ float qrow[MM];

    for (int i = tid; i < MM * HD; i += 64)
        kvs[i / HD][i % HD] = kv[(size_t)bh * MM * HD + i];
    kss[tid] = ksum[(size_t)bh * MM + tid];
    __syncthreads();

    int s0 = blockIdx.x * 64;
    for (int r = 0; r < 64; r++) {
        int s = s0 + r;
        qrow[tid] = qp[((size_t)bh * SS + s) * MM + tid];
        __syncthreads();

        float o = 0.f, nr = 0.f;
        #pragma unroll
        for (int mm = 0; mm < MM; mm++) {
            float qv = qrow[mm];
            o = fmaf(qv, kvs[mm][tid], o);
            nr = fmaf(qv, kss[mm], nr);
        }
        ctx[((size_t)(b * SS + s)) * HH + h * HD + tid] = o / (nr + EPSF);
        __syncthreads();
    }
}

// ---------------- launch ----------------
extern "C" void kernel_launch(void* const* d_in, const int* in_sizes, int n_in,
                              void* d_out, int out_size) {
    const float* X  = (const float*)d_in[0];
    const float* Wq = (const float*)d_in[1];
    const float* bq = (const float*)d_in[2];
    const float* Wk = (const float*)d_in[3];
    const float* bk = (const float*)d_in[4];
    const float* Wv = (const float*)d_in[5];
    const float* bv = (const float*)d_in[6];
    const float* Wo = (const float*)d_in[7];
    const float* bo = (const float*)d_in[8];
    const float* P  = (const float*)d_in[9];
    float* out = (float*)d_out;

    float *q, *k, *v, *qp, *kp, *kv, *ksum, *ctx;
    cudaGetSymbolAddress((void**)&q,    g_q);
    cudaGetSymbolAddress((void**)&k,    g_k);
    cudaGetSymbolAddress((void**)&v,    g_v);
    cudaGetSymbolAddress((void**)&qp,   g_qp);
    cudaGetSymbolAddress((void**)&kp,   g_kp);
    cudaGetSymbolAddress((void**)&kv,   g_kv);
    cudaGetSymbolAddress((void**)&ksum, g_ksum);
    cudaGetSymbolAddress((void**)&ctx,  g_ctx);

    dim3 gemmGrid(HH / 64, NTOK / 64);   // (12, 512)
    dim3 gemmBlock(256);

    // Q/K/V projections
    gemm_bias_kernel<<<gemmGrid, gemmBlock>>>(X, Wq, bq, q, NTOK, HH, HH);
    gemm_bias_kernel<<<gemmGrid, gemmBlock>>>(X, Wk, bk, k, NTOK, HH, HH);
    gemm_bias_kernel<<<gemmGrid, gemmBlock>>>(X, Wv, bv, v, NTOK, HH, HH);

    // random-feature + exp
    dim3 projGrid(SS / 64, BHS);
    proj_exp_kernel<<<projGrid, 64>>>(q, P, qp);
    proj_exp_kernel<<<projGrid, 64>>>(k, P, kp);

    // zero kv scratch
    int nz = BHS * MM * HD + BHS * MM;
    zero_kernel<<<(nz + 255) / 256, 256>>>(kv, nz);  // kv followed by ksum? (separate arrays)
    // zero ksum separately (arrays are distinct symbols)
    zero_kernel<<<(BHS * MM + 255) / 256, 256>>>(ksum, BHS * MM);

    // kv summary
    dim3 kvGrid(64, BHS);
    kv_accum_kernel<<<kvGrid, 256>>>(kp, v, kv, ksum);

    // recombine + normalize
    qkv_norm_kernel<<<projGrid, 64>>>(qp, kv, ksum, ctx);

    // output projection -> d_out
    gemm_bias_kernel<<<gemmGrid, gemmBlock>>>(ctx, Wo, bo, out, NTOK, HH, HH);
}

// round 4
// speedup vs baseline: 2.9543x; 2.9543x over previous
#include <cuda_runtime.h>
#include <cuda_bf16.h>
#include <cstdint>
#include <math.h>

#define BB 4
#define SS 8192
#define HH 768
#define NH 12
#define HD 64
#define MM 64
#define NTOK (BB * SS)          // 32768
#define BHS (BB * NH)           // 48
#define EPSF 1e-6f

// ======================= helpers =======================
__device__ __forceinline__ uint32_t smem_u32(const void* p) {
    uint32_t a;
    asm("{ .reg .u64 t; cvta.to.shared.u64 t, %1; cvt.u32.u64 %0, t; }" : "=r"(a) : "l"(p));
    return a;
}

#define SWZ(o) ((o) ^ (((o) >> 3) & 0x70))

__device__ __forceinline__ void cpa16(uint32_t dst, const void* src) {
    asm volatile("cp.async.cg.shared.global [%0], [%1], 16;" :: "r"(dst), "l"(src));
}
#define CP_COMMIT() asm volatile("cp.async.commit_group;" ::: "memory")
#define CP_WAIT0()  asm volatile("cp.async.wait_group 0;" ::: "memory")
#define CP_WAIT1()  asm volatile("cp.async.wait_group 1;" ::: "memory")

__device__ __forceinline__ void ldsm4(uint32_t* r, uint32_t addr) {
    asm volatile("ldmatrix.sync.aligned.m8n8.x4.shared.b16 {%0,%1,%2,%3}, [%4];"
        : "=r"(r[0]), "=r"(r[1]), "=r"(r[2]), "=r"(r[3]) : "r"(addr));
}
__device__ __forceinline__ void mma16816(float* c, const uint32_t* a, const uint32_t* b) {
    asm volatile("mma.sync.aligned.m16n8k16.row.col.f32.bf16.bf16.f32 "
        "{%0,%1,%2,%3}, {%4,%5,%6,%7}, {%8,%9}, {%0,%1,%2,%3};"
        : "+f"(c[0]), "+f"(c[1]), "+f"(c[2]), "+f"(c[3])
        : "r"(a[0]), "r"(a[1]), "r"(a[2]), "r"(a[3]), "r"(b[0]), "r"(b[1]));
}

__device__ __forceinline__ void split2(float v, __nv_bfloat16& hi, __nv_bfloat16& lo) {
    hi = __float2bfloat16(v);
    lo = __float2bfloat16(v - __bfloat162float(hi));
}

// load a [rows x 64] bf16 chunk (row -> 128B swizzled) via cp.async
__device__ __forceinline__ void cp_tile64(const __nv_bfloat16* __restrict__ g, int row0,
                                          int ld, int kc0, uint32_t sbase, int tid, int rows) {
    int total = rows * 8;
    for (int i = tid; i < total; i += 256) {
        int r = i >> 3, j = i & 7;
        uint32_t bo = (uint32_t)(r * 128 + j * 16);
        cpa16(sbase + SWZ(bo), g + (size_t)(row0 + r) * ld + kc0 + j * 8);
    }
}

// ======================= scratch =======================
__device__ __nv_bfloat16 g_xhi[(size_t)NTOK * HH], g_xlo[(size_t)NTOK * HH];
__device__ __nv_bfloat16 g_wqph[(size_t)HH * HH], g_wqpl[(size_t)HH * HH];
__device__ __nv_bfloat16 g_wkph[(size_t)HH * HH], g_wkpl[(size_t)HH * HH];
__device__ __nv_bfloat16 g_wvth[(size_t)HH * HH], g_wvtl[(size_t)HH * HH];
__device__ __nv_bfloat16 g_woth[(size_t)HH * HH], g_wotl[(size_t)HH * HH];
__device__ float         g_bqf[HH], g_bkf[HH];
__device__ __nv_bfloat16 g_qphi[(size_t)NTOK * HH], g_qplo[(size_t)NTOK * HH];
__device__ float         g_kpf[(size_t)BHS * SS * MM];
__device__ float         g_v[(size_t)NTOK * HH];
__device__ float         g_kv[(size_t)BHS * MM * HD];
__device__ float         g_ksum[(size_t)BHS * MM];
__device__ __nv_bfloat16 g_kvxh[(size_t)BHS * 128 * 64], g_kvxl[(size_t)BHS * 128 * 64];
__device__ __nv_bfloat16 g_ctxh[(size_t)NTOK * HH], g_ctxl[(size_t)NTOK * HH];

// ======================= preprocessing =======================
__global__ void split_f32_kernel(const float* __restrict__ x,
                                 __nv_bfloat16* __restrict__ hi,
                                 __nv_bfloat16* __restrict__ lo, size_t n) {
    for (size_t i = (size_t)blockIdx.x * blockDim.x + threadIdx.x; i < n;
         i += (size_t)gridDim.x * blockDim.x) {
        __nv_bfloat16 h, l;
        split2(x[i], h, l);
        hi[i] = h; lo[i] = l;
    }
}

// W[K=768][N=768] -> Wt[n][k], split hi/lo
__global__ void wt_prep_kernel(const float* __restrict__ W,
                               __nv_bfloat16* __restrict__ hi,
                               __nv_bfloat16* __restrict__ lo) {
    __shared__ float t[32][33];
    int bx = blockIdx.x * 32, by = blockIdx.y * 32;
    int x = threadIdx.x, y = threadIdx.y;   // block (32,8)
    #pragma unroll
    for (int i = 0; i < 32; i += 8)
        t[y + i][x] = W[(size_t)(by + y + i) * HH + bx + x];
    __syncthreads();
    #pragma unroll
    for (int i = 0; i < 32; i += 8) {
        float v = t[x][y + i];
        __nv_bfloat16 h, l; split2(v, h, l);
        size_t o = (size_t)(bx + y + i) * HH + by + x;
        hi[o] = h; lo[o] = l;
    }
}

// Wt_fold[n=h*64+m][k=i] = sum_d W[i][h*64+d] * P[h][d][m]
__global__ void fold_w_kernel(const float* __restrict__ W, const float* __restrict__ P,
                              __nv_bfloat16* __restrict__ hi, __nv_bfloat16* __restrict__ lo) {
    int h = blockIdx.y;
    int i0 = blockIdx.x * 16;
    __shared__ float Ps[64][65];
    __shared__ float Ws[16][65];
    for (int t = threadIdx.x; t < 64 * 64; t += 256)
        Ps[t >> 6][t & 63] = P[(size_t)h * 4096 + t];
    for (int t = threadIdx.x; t < 16 * 64; t += 256)
        Ws[t >> 6][t & 63] = W[(size_t)(i0 + (t >> 6)) * HH + h * 64 + (t & 63)];
    __syncthreads();
    for (int t = threadIdx.x; t < 16 * 64; t += 256) {
        int il = t >> 6, m = t & 63;
        float s = 0.f;
        #pragma unroll
        for (int d = 0; d < 64; d++) s = fmaf(Ws[il][d], Ps[d][m], s);
        __nv_bfloat16 hh, ll; split2(s, hh, ll);
        size_t o = (size_t)(h * 64 + m) * HH + i0 + il;
        hi[o] = hh; lo[o] = ll;
    }
}

// b_fold[h*64+m] = sum_d b[h*64+d] * P[h][d][m]
__global__ void fold_b_kernel(const float* __restrict__ b, const float* __restrict__ P,
                              float* __restrict__ bout) {
    int h = blockIdx.x, m = threadIdx.x;
    float s = 0.f;
    for (int d = 0; d < 64; d++)
        s = fmaf(b[h * 64 + d], P[(size_t)h * 4096 + d * 64 + m], s);
    bout[h * 64 + m] = s;
}

// kv [bh][m][d], ksum [bh][m] -> kvx [bh][n][k]: n<64: kv[k][n]; n==64: ksum[k]; else 0
__global__ void kvx_prep_kernel(const float* __restrict__ kvf,
                                const float* __restrict__ ksum,
                                __nv_bfloat16* __restrict__ hi,
                                __nv_bfloat16* __restrict__ lo) {
    int bh = blockIdx.x;
    for (int i = threadIdx.x; i < 128 * 64; i += 256) {
        int n = i >> 6, kk = i & 63;
        float v = 0.f;
        if (n < 64)       v = kvf[((size_t)bh * MM + kk) * HD + n];
        else if (n == 64) v = ksum[(size_t)bh * MM + kk];
        __nv_bfloat16 h, l; split2(v, h, l);
        hi[(size_t)bh * 128 * 64 + i] = h;
        lo[(size_t)bh * 128 * 64 + i] = l;
    }
}

__global__ void zero_kernel(float* __restrict__ p, int n) {
    int i = blockIdx.x * blockDim.x + threadIdx.x;
    if (i < n) p[i] = 0.f;
}

// ======================= big GEMM (mma.sync bf16, split-3) =======================
// C[128,128] tile; A[tok][768] hi/lo, B=Wt[n][768] hi/lo. K=768.
// mode 0: fp32 out + bias. mode 1: split bf16 out + bias.
// mode 2: exp(x+bias - rowgroupmax) -> split bf16 [tok][768]
// mode 3: exp(...) -> fp32 kp [bh][s][64]
#define SA_HI 0
#define SA_LO 16384
#define SB_HI 32768
#define SB_LO 49152
#define STAGE 65536

__global__ __launch_bounds__(256, 1)
void gemm_tc_kernel(const __nv_bfloat16* __restrict__ Ahi, const __nv_bfloat16* __restrict__ Alo,
                    const __nv_bfloat16* __restrict__ Bhi, const __nv_bfloat16* __restrict__ Blo,
                    const float* __restrict__ bias, float* __restrict__ Cf,
                    __nv_bfloat16* __restrict__ Chi, __nv_bfloat16* __restrict__ Clo, int mode) {
    extern __shared__ char smem[];
    uint32_t sb = smem_u32(smem);
    int tid = threadIdx.x, wid = tid >> 5, lane = tid & 31;
    int row0 = blockIdx.y * 128, col0 = blockIdx.x * 128;
    int wm = (wid & 1) * 64, wn = (wid >> 1) * 32;

    float acc[4][4][4];
    #pragma unroll
    for (int a = 0; a < 4; a++)
        #pragma unroll
        for (int bq = 0; bq < 4; bq++)
            #pragma unroll
            for (int cq = 0; cq < 4; cq++) acc[a][bq][cq] = 0.f;

    // prologue
    {
        uint32_t s0 = sb;
        cp_tile64(Ahi, row0, HH, 0, s0 + SA_HI, tid, 128);
        cp_tile64(Alo, row0, HH, 0, s0 + SA_LO, tid, 128);
        cp_tile64(Bhi, col0, HH, 0, s0 + SB_HI, tid, 128);
        cp_tile64(Blo, col0, HH, 0, s0 + SB_LO, tid, 128);
        CP_COMMIT();
    }

    for (int c = 0; c < 12; c++) {
        int buf = c & 1;
        if (c + 1 < 12) {
            uint32_t sn = sb + (buf ^ 1) * STAGE;
            int kc = (c + 1) * 64;
            cp_tile64(Ahi, row0, HH, kc, sn + SA_HI, tid, 128);
            cp_tile64(Alo, row0, HH, kc, sn + SA_LO, tid, 128);
            cp_tile64(Bhi, col0, HH, kc, sn + SB_HI, tid, 128);
            cp_tile64(Blo, col0, HH, kc, sn + SB_LO, tid, 128);
            CP_COMMIT();
            CP_WAIT1();
        } else {
            CP_WAIT0();
        }
        __syncthreads();

        uint32_t s0 = sb + buf * STAGE;
        #pragma unroll
        for (int ks = 0; ks < 4; ks++) {
            uint32_t bh2[2][4], bl2[2][4];
            #pragma unroll
            for (int half = 0; half < 2; half++) {
                int nr = wn + half * 16 + (lane & 7) + ((lane & 16) ? 8 : 0);
                int kb = ks * 32 + ((lane & 8) ? 16 : 0);
                ldsm4(bh2[half], s0 + SB_HI + SWZ((uint32_t)(nr * 128 + kb)));
                ldsm4(bl2[half], s0 + SB_LO + SWZ((uint32_t)(nr * 128 + kb)));
            }
            #pragma unroll
            for (int im = 0; im < 4; im++) {
                int rowa = wm + im * 16 + (lane & 15);
                int ka = ks * 32 + ((lane & 16) ? 16 : 0);
                uint32_t ah[4], al[4];
                ldsm4(ah, s0 + SA_HI + SWZ((uint32_t)(rowa * 128 + ka)));
                ldsm4(al, s0 + SA_LO + SWZ((uint32_t)(rowa * 128 + ka)));
                #pragma unroll
                for (int in = 0; in < 4; in++) {
                    const uint32_t* bhp = &bh2[in >> 1][(in & 1) * 2];
                    const uint32_t* blp = &bl2[in >> 1][(in & 1) * 2];
                    mma16816(acc[im][in], ah, bhp);
                    mma16816(acc[im][in], al, bhp);
                    mma16816(acc[im][in], ah, blp);
                }
            }
        }
        __syncthreads();
    }

    // stage accumulators to smem
    float* fs = reinterpret_cast<float*>(smem);
    #pragma unroll
    for (int im = 0; im < 4; im++)
        #pragma unroll
        for (int in = 0; in < 4; in++) {
            int r = wm + im * 16 + (lane >> 2);
            int cc = wn + in * 8 + (lane & 3) * 2;
            fs[r * 132 + cc]           = acc[im][in][0];
            fs[r * 132 + cc + 1]       = acc[im][in][1];
            fs[(r + 8) * 132 + cc]     = acc[im][in][2];
            fs[(r + 8) * 132 + cc + 1] = acc[im][in][3];
        }
    __syncthreads();

    if (mode <= 1) {
        for (int i = tid; i < 128 * 128; i += 256) {
            int r = i >> 7, cc = i & 127;
            float v = fs[r * 132 + cc] + bias[col0 + cc];
            size_t o = (size_t)(row0 + r) * HH + col0 + cc;
            if (mode == 0) Cf[o] = v;
            else { __nv_bfloat16 h, l; split2(v, h, l); Chi[o] = h; Clo[o] = l; }
        }
    } else {
        int r = tid >> 1, g = tid & 1;
        int cb = g * 64;
        float mx = -1e30f;
        #pragma unroll
        for (int m = 0; m < 64; m++)
            mx = fmaxf(mx, fs[r * 132 + cb + m] + bias[col0 + cb + m]);
        int tok = row0 + r;
        if (mode == 2) {
            size_t ob = (size_t)tok * HH + col0 + cb;
            for (int m = 0; m < 64; m++) {
                float e = __expf(fs[r * 132 + cb + m] + bias[col0 + cb + m] - mx);
                __nv_bfloat16 h, l; split2(e, h, l);
                Chi[ob + m] = h; Clo[ob + m] = l;
            }
        } else {
            int b = tok >> 13, s = tok & (SS - 1);
            int h = (col0 + cb) >> 6;
            size_t ob = ((size_t)(b * NH + h) * SS + s) * MM;
            for (int m = 0; m < 64; m++)
                Cf[ob + m] = __expf(fs[r * 132 + cb + m] + bias[col0 + cb + m] - mx);
        }
    }
}

// ======================= qkv GEMM + normalize =======================
// A = qp hi/lo [tok][768] at col h*64 (K=64). B = kvx [bh][128][64].
__global__ __launch_bounds__(256, 1)
void qkv_tc_kernel(const __nv_bfloat16* __restrict__ QPhi, const __nv_bfloat16* __restrict__ QPlo,
                   const __nv_bfloat16* __restrict__ KVhi, const __nv_bfloat16* __restrict__ KVlo,
                   __nv_bfloat16* __restrict__ Chi, __nv_bfloat16* __restrict__ Clo) {
    extern __shared__ char smem[];
    uint32_t sb = smem_u32(smem);
    int tid = threadIdx.x, wid = tid >> 5, lane = tid & 31;
    int bh = blockIdx.y, b = bh / NH, h = bh % NH;
    int s0 = blockIdx.x * 128;
    int row0 = b * SS + s0;
    int wm = (wid & 1) * 64, wn = (wid >> 1) * 32;

    cp_tile64(QPhi + h * 64, row0, HH, 0, sb + SA_HI, tid, 128);
    cp_tile64(QPlo + h * 64, row0, HH, 0, sb + SA_LO, tid, 128);
    cp_tile64(KVhi + (size_t)bh * 128 * 64, 0, 64, 0, sb + SB_HI, tid, 128);
    cp_tile64(KVlo + (size_t)bh * 128 * 64, 0, 64, 0, sb + SB_LO, tid, 128);
    CP_COMMIT();
    CP_WAIT0();
    __syncthreads();

    float acc[4][4][4];
    #pragma unroll
    for (int a = 0; a < 4; a++)
        #pragma unroll
        for (int bq = 0; bq < 4; bq++)
            #pragma unroll
            for (int cq = 0; cq < 4; cq++) acc[a][bq][cq] = 0.f;

    #pragma unroll
    for (int ks = 0; ks < 4; ks++) {
        uint32_t bh2[2][4], bl2[2][4];
        #pragma unroll
        for (int half = 0; half < 2; half++) {
            int nr = wn + half * 16 + (lane & 7) + ((lane & 16) ? 8 : 0);
            int kb = ks * 32 + ((lane & 8) ? 16 : 0);
            ldsm4(bh2[half], sb + SB_HI + SWZ((uint32_t)(nr * 128 + kb)));
            ldsm4(bl2[half], sb + SB_LO + SWZ((uint32_t)(nr * 128 + kb)));
        }
        #pragma unroll
        for (int im = 0; im < 4; im++) {
            int rowa = wm + im * 16 + (lane & 15);
            int ka = ks * 32 + ((lane & 16) ? 16 : 0);
            uint32_t ah[4], al[4];
            ldsm4(ah, sb + SA_HI + SWZ((uint32_t)(rowa * 128 + ka)));
            ldsm4(al, sb + SA_LO + SWZ((uint32_t)(rowa * 128 + ka)));
            #pragma unroll
            for (int in = 0; in < 4; in++) {
                const uint32_t* bhp = &bh2[in >> 1][(in & 1) * 2];
                const uint32_t* blp = &bl2[in >> 1][(in & 1) * 2];
                mma16816(acc[im][in], ah, bhp);
                mma16816(acc[im][in], al, bhp);
                mma16816(acc[im][in], ah, blp);
            }
        }
    }
    __syncthreads();

    float* fs = reinterpret_cast<float*>(smem);
    #pragma unroll
    for (int im = 0; im < 4; im++)
        #pragma unroll
        for (int in = 0; in < 4; in++) {
            int r = wm + im * 16 + (lane >> 2);
            int cc = wn + in * 8 + (lane & 3) * 2;
            fs[r * 132 + cc]           = acc[im][in][0];
            fs[r * 132 + cc + 1]       = acc[im][in][1];
            fs[(r + 8) * 132 + cc]     = acc[im][in][2];
            fs[(r + 8) * 132 + cc + 1] = acc[im][in][3];
        }
    __syncthreads();

    for (int i = tid; i < 128 * 64; i += 256) {
        int r = i >> 6, d = i & 63;
        float inv = 1.0f / (fs[r * 132 + 64] + EPSF);
        float v = fs[r * 132 + d] * inv;
        __nv_bfloat16 hh, ll; split2(v, hh, ll);
        size_t o = (size_t)(row0 + r) * HH + h * HD + d;
        Chi[o] = hh; Clo[o] = ll;
    }
}

// ======================= kv summary (SIMT, atomics) =======================
__global__ void kv_accum_kernel(const float* __restrict__ kp,   // [BHS, SS, MM]
                                const float* __restrict__ v,    // [NTOK, HH]
                                float* __restrict__ kv,         // [BHS, MM, HD]
                                float* __restrict__ ksum) {     // [BHS, MM]
    const int SPLITS = 64;
    const int ROWS = SS / SPLITS;   // 128
    const int CH = 16;
    int bh = blockIdx.y;
    int b = bh / NH, h = bh % NH;
    int split = blockIdx.x;
    int tid = threadIdx.x;
    int m = tid % 64;
    int dg = tid / 64;

    __shared__ float kps[CH][MM];
    __shared__ float vs[CH][HD];

    float acc[16] = {};
    float ks = 0.f;
    int n0 = split * ROWS;
    for (int c0 = 0; c0 < ROWS; c0 += CH) {
        for (int i = tid; i < CH * 64; i += 256) {
            int r = i / 64, cc = i % 64;
            int n = n0 + c0 + r;
            kps[r][cc] = kp[((size_t)bh * SS + n) * MM + cc];
            vs[r][cc]  = v[((size_t)(b * SS + n)) * HH + h * HD + cc];
        }
        __syncthreads();
        #pragma unroll
        for (int r = 0; r < CH; r++) {
            float a = kps[r][m];
            if (dg == 0) ks += a;
            #pragma unroll
            for (int j = 0; j < 16; j++)
                acc[j] = fmaf(a, vs[r][dg * 16 + j], acc[j]);
        }
        __syncthreads();
    }
    float* kvp = kv + ((size_t)bh * MM + m) * HD + dg * 16;
    #pragma unroll
    for (int j = 0; j < 16; j++) atomicAdd(&kvp[j], acc[j]);
    if (dg == 0) atomicAdd(&ksum[(size_t)bh * MM + m], ks);
}

// ======================= launch =======================
extern "C" void kernel_launch(void* const* d_in, const int* in_sizes, int n_in,
                              void* d_out, int out_size) {
    const float* X  = (const float*)d_in[0];
    const float* Wq = (const float*)d_in[1];
    const float* bq = (const float*)d_in[2];
    const float* Wk = (const float*)d_in[3];
    const float* bk = (const float*)d_in[4];
    const float* Wv = (const float*)d_in[5];
    const float* bv = (const float*)d_in[6];
    const float* Wo = (const float*)d_in[7];
    const float* bo = (const float*)d_in[8];
    const float* P  = (const float*)d_in[9];
    float* out = (float*)d_out;

    __nv_bfloat16 *xhi, *xlo, *wqph, *wqpl, *wkph, *wkpl, *wvth, *wvtl, *woth, *wotl;
    __nv_bfloat16 *qphi, *qplo, *kvxh, *kvxl, *ctxh, *ctxl;
    float *bqf, *bkf, *vf, *kpf, *kvf, *ksum;
    cudaGetSymbolAddress((void**)&xhi, g_xhi);   cudaGetSymbolAddress((void**)&xlo, g_xlo);
    cudaGetSymbolAddress((void**)&wqph, g_wqph); cudaGetSymbolAddress((void**)&wqpl, g_wqpl);
    cudaGetSymbolAddress((void**)&wkph, g_wkph); cudaGetSymbolAddress((void**)&wkpl, g_wkpl);
    cudaGetSymbolAddress((void**)&wvth, g_wvth); cudaGetSymbolAddress((void**)&wvtl, g_wvtl);
    cudaGetSymbolAddress((void**)&woth, g_woth); cudaGetSymbolAddress((void**)&wotl, g_wotl);
    cudaGetSymbolAddress((void**)&bqf, g_bqf);   cudaGetSymbolAddress((void**)&bkf, g_bkf);
    cudaGetSymbolAddress((void**)&qphi, g_qphi); cudaGetSymbolAddress((void**)&qplo, g_qplo);
    cudaGetSymbolAddress((void**)&kpf, g_kpf);   cudaGetSymbolAddress((void**)&vf, g_v);
    cudaGetSymbolAddress((void**)&kvf, g_kv);    cudaGetSymbolAddress((void**)&ksum, g_ksum);
    cudaGetSymbolAddress((void**)&kvxh, g_kvxh); cudaGetSymbolAddress((void**)&kvxl, g_kvxl);
    cudaGetSymbolAddress((void**)&ctxh, g_ctxh); cudaGetSymbolAddress((void**)&ctxl, g_ctxl);

    cudaFuncSetAttribute(gemm_tc_kernel, cudaFuncAttributeMaxDynamicSharedMemorySize, 131072);
    cudaFuncSetAttribute(qkv_tc_kernel,  cudaFuncAttributeMaxDynamicSharedMemorySize, 69632);

    // preprocessing
    split_f32_kernel<<<4096, 256>>>(X, xhi, xlo, (size_t)NTOK * HH);
    dim3 wtg(HH / 32, HH / 32);
    wt_prep_kernel<<<wtg, dim3(32, 8)>>>(Wv, wvth, wvtl);
    wt_prep_kernel<<<wtg, dim3(32, 8)>>>(Wo, woth, wotl);
    dim3 fwg(HH / 16, NH);
    fold_w_kernel<<<fwg, 256>>>(Wq, P, wqph, wqpl);
    fold_w_kernel<<<fwg, 256>>>(Wk, P, wkph, wkpl);
    fold_b_kernel<<<NH, 64>>>(bq, P, bqf);
    fold_b_kernel<<<NH, 64>>>(bk, P, bkf);

    dim3 gg(HH / 128, NTOK / 128);    // (6, 256)
    // qp = exp(X@Wqp + bqf - rowmax)  (split bf16, [tok][768])
    gemm_tc_kernel<<<gg, 256, 131072>>>(xhi, xlo, wqph, wqpl, bqf, nullptr, qphi, qplo, 2);
    // kp = exp(X@Wkp + bkf - rowmax)  (fp32, [bh][s][64])
    gemm_tc_kernel<<<gg, 256, 131072>>>(xhi, xlo, wkph, wkpl, bkf, kpf, nullptr, nullptr, 3);
    // v = X@Wv + bv  (fp32)
    gemm_tc_kernel<<<gg, 256, 131072>>>(xhi, xlo, wvth, wvtl, bv, vf, nullptr, nullptr, 0);

    // kv summary
    zero_kernel<<<(BHS * MM * HD + 255) / 256, 256>>>(kvf, BHS * MM * HD);
    zero_kernel<<<(BHS * MM + 255) / 256, 256>>>(ksum, BHS * MM);
    dim3 kvg(64, BHS);
    kv_accum_kernel<<<kvg, 256>>>(kpf, vf, kvf, ksum);
    kvx_prep_kernel<<<BHS, 256>>>(kvf, ksum, kvxh, kvxl);

    // recombine + normalize -> ctx split bf16
    dim3 pg(SS / 128, BHS);           // (64, 48)
    qkv_tc_kernel<<<pg, 256, 69632>>>(qphi, qplo, kvxh, kvxl, ctxh, ctxl);

    // out = ctx@Wo + bo (fp32)
    gemm_tc_kernel<<<gg, 256, 131072>>>(ctxh, ctxl, woth, wotl, bo, out, nullptr, nullptr, 0);
}

// round 6
// speedup vs baseline: 3.1607x; 1.0698x over previous
#include <cuda_runtime.h>
#include <cuda_bf16.h>
#include <cstdint>
#include <math.h>

#define BB 4
#define SS 8192
#define HH 768
#define NH 12
#define HD 64
#define MM 64
#define NTOK (BB * SS)          // 32768
#define BHS (BB * NH)           // 48
#define EPSF 1e-6f

// ======================= helpers =======================
__device__ __forceinline__ uint32_t smem_u32(const void* p) {
    uint32_t a;
    asm("{ .reg .u64 t; cvta.to.shared.u64 t, %1; cvt.u32.u64 %0, t; }" : "=r"(a) : "l"(p));
    return a;
}

#define SWZ(o) ((o) ^ (((o) >> 3) & 0x70))

__device__ __forceinline__ void cpa16(uint32_t dst, const void* src) {
    asm volatile("cp.async.cg.shared.global [%0], [%1], 16;" :: "r"(dst), "l"(src));
}
#define CP_COMMIT() asm volatile("cp.async.commit_group;" ::: "memory")
#define CP_WAIT0()  asm volatile("cp.async.wait_group 0;" ::: "memory")
#define CP_WAIT1()  asm volatile("cp.async.wait_group 1;" ::: "memory")
#define CP_WAIT2()  asm volatile("cp.async.wait_group 2;" ::: "memory")

__device__ __forceinline__ void ldsm4(uint32_t* r, uint32_t addr) {
    asm volatile("ldmatrix.sync.aligned.m8n8.x4.shared.b16 {%0,%1,%2,%3}, [%4];"
        : "=r"(r[0]), "=r"(r[1]), "=r"(r[2]), "=r"(r[3]) : "r"(addr));
}
__device__ __forceinline__ void mma16816(float* c, const uint32_t* a, const uint32_t* b) {
    asm volatile("mma.sync.aligned.m16n8k16.row.col.f32.bf16.bf16.f32 "
        "{%0,%1,%2,%3}, {%4,%5,%6,%7}, {%8,%9}, {%0,%1,%2,%3};"
        : "+f"(c[0]), "+f"(c[1]), "+f"(c[2]), "+f"(c[3])
        : "r"(a[0]), "r"(a[1]), "r"(a[2]), "r"(a[3]), "r"(b[0]), "r"(b[1]));
}

__device__ __forceinline__ void split2(float v, __nv_bfloat16& hi, __nv_bfloat16& lo) {
    hi = __float2bfloat16(v);
    lo = __float2bfloat16(v - __bfloat162float(hi));
}

// load a [rows x 64] bf16 chunk (row -> 128B swizzled) via cp.async
__device__ __forceinline__ void cp_tile64(const __nv_bfloat16* __restrict__ g, int row0,
                                          int ld, int kc0, uint32_t sbase, int tid, int rows) {
    int total = rows * 8;
    for (int i = tid; i < total; i += 256) {
        int r = i >> 3, j = i & 7;
        uint32_t bo = (uint32_t)(r * 128 + j * 16);
        cpa16(sbase + SWZ(bo), g + (size_t)(row0 + r) * ld + kc0 + j * 8);
    }
}

// ======================= scratch =======================
__device__ __nv_bfloat16 g_xhi[(size_t)NTOK * HH], g_xlo[(size_t)NTOK * HH];
__device__ __nv_bfloat16 g_wqph[(size_t)HH * HH], g_wqpl[(size_t)HH * HH];
__device__ __nv_bfloat16 g_wkph[(size_t)HH * HH], g_wkpl[(size_t)HH * HH];
__device__ __nv_bfloat16 g_wvth[(size_t)HH * HH], g_wvtl[(size_t)HH * HH];
__device__ __nv_bfloat16 g_woth[(size_t)HH * HH], g_wotl[(size_t)HH * HH];
__device__ float         g_bqf[HH], g_bkf[HH];
__device__ __nv_bfloat16 g_qphi[(size_t)NTOK * HH], g_qplo[(size_t)NTOK * HH];
__device__ float         g_kpf[(size_t)BHS * SS * MM];
__device__ float         g_v[(size_t)NTOK * HH];
__device__ float         g_kv[(size_t)BHS * MM * HD];
__device__ float         g_ksum[(size_t)BHS * MM];
__device__ __nv_bfloat16 g_kvxh[(size_t)BHS * 128 * 64], g_kvxl[(size_t)BHS * 128 * 64];
__device__ __nv_bfloat16 g_ctxh[(size_t)NTOK * HH], g_ctxl[(size_t)NTOK * HH];

// ======================= preprocessing =======================
__global__ void split_f32_kernel(const float* __restrict__ x,
                                 __nv_bfloat16* __restrict__ hi,
                                 __nv_bfloat16* __restrict__ lo, size_t n2) {
    const float2* x2 = reinterpret_cast<const float2*>(x);
    __nv_bfloat162* h2 = reinterpret_cast<__nv_bfloat162*>(hi);
    __nv_bfloat162* l2 = reinterpret_cast<__nv_bfloat162*>(lo);
    for (size_t i = (size_t)blockIdx.x * blockDim.x + threadIdx.x; i < n2;
         i += (size_t)gridDim.x * blockDim.x) {
        float2 v = x2[i];
        __nv_bfloat16 hx, lx, hy, ly;
        split2(v.x, hx, lx);
        split2(v.y, hy, ly);
        h2[i] = __nv_bfloat162(hx, hy);
        l2[i] = __nv_bfloat162(lx, ly);
    }
}

// W[K=768][N=768] -> Wt[n][k], split hi/lo; z selects (Wv, Wo)
__global__ void wt_prep_kernel(const float* __restrict__ Wv, const float* __restrict__ Wo,
                               __nv_bfloat16* __restrict__ hiV, __nv_bfloat16* __restrict__ loV,
                               __nv_bfloat16* __restrict__ hiO, __nv_bfloat16* __restrict__ loO) {
    const float* W = blockIdx.z ? Wo : Wv;
    __nv_bfloat16* hi = blockIdx.z ? hiO : hiV;
    __nv_bfloat16* lo = blockIdx.z ? loO : loV;
    __shared__ float t[32][33];
    int bx = blockIdx.x * 32, by = blockIdx.y * 32;
    int x = threadIdx.x, y = threadIdx.y;   // block (32,8)
    #pragma unroll
    for (int i = 0; i < 32; i += 8)
        t[y + i][x] = W[(size_t)(by + y + i) * HH + bx + x];
    __syncthreads();
    #pragma unroll
    for (int i = 0; i < 32; i += 8) {
        float v = t[x][y + i];
        __nv_bfloat16 h, l; split2(v, h, l);
        size_t o = (size_t)(bx + y + i) * HH + by + x;
        hi[o] = h; lo[o] = l;
    }
}

// Wt_fold[n=h*64+m][k=i] = sum_d W[i][h*64+d] * P[h][d][m]; 64 i-rows per block
__global__ void fold_w_kernel(const float* __restrict__ W, const float* __restrict__ P,
                              __nv_bfloat16* __restrict__ hi, __nv_bfloat16* __restrict__ lo) {
    int h = blockIdx.y;
    int i0 = blockIdx.x * 64;
    __shared__ float Ps[64][65];
    __shared__ float Ws[64][65];
    for (int t = threadIdx.x; t < 64 * 64; t += 256) {
        Ps[t >> 6][t & 63] = P[(size_t)h * 4096 + t];
        Ws[t >> 6][t & 63] = W[(size_t)(i0 + (t >> 6)) * HH + h * 64 + (t & 63)];
    }
    __syncthreads();
    for (int t = threadIdx.x; t < 64 * 64; t += 256) {
        int il = t >> 6, m = t & 63;
        float s = 0.f;
        #pragma unroll
        for (int d = 0; d < 64; d++) s = fmaf(Ws[il][d], Ps[d][m], s);
        __nv_bfloat16 hh, ll; split2(s, hh, ll);
        size_t o = (size_t)(h * 64 + m) * HH + i0 + il;
        hi[o] = hh; lo[o] = ll;
    }
}

// b_fold[h*64+m] = sum_d b[h*64+d] * P[h][d][m]; y selects (bq, bk)
__global__ void fold_b_kernel(const float* __restrict__ bq, const float* __restrict__ bk,
                              const float* __restrict__ P,
                              float* __restrict__ bqo, float* __restrict__ bko) {
    const float* b = blockIdx.y ? bk : bq;
    float* bout = blockIdx.y ? bko : bqo;
    int h = blockIdx.x, m = threadIdx.x;
    float s = 0.f;
    for (int d = 0; d < 64; d++)
        s = fmaf(b[h * 64 + d], P[(size_t)h * 4096 + d * 64 + m], s);
    bout[h * 64 + m] = s;
}

// kv [bh][m][d], ksum [bh][m] -> kvx [bh][n][k] (80 rows): n<64: kv[k][n]; n==64: ksum[k]; 65..79: 0
__global__ void kvx_prep_kernel(const float* __restrict__ kvf,
                                const float* __restrict__ ksum,
                                __nv_bfloat16* __restrict__ hi,
                                __nv_bfloat16* __restrict__ lo) {
    int bh = blockIdx.x;
    for (int i = threadIdx.x; i < 80 * 64; i += 256) {
        int n = i >> 6, kk = i & 63;
        float v = 0.f;
        if (n < 64)       v = kvf[((size_t)bh * MM + kk) * HD + n];
        else if (n == 64) v = ksum[(size_t)bh * MM + kk];
        __nv_bfloat16 h, l; split2(v, h, l);
        hi[(size_t)bh * 128 * 64 + i] = h;
        lo[(size_t)bh * 128 * 64 + i] = l;
    }
}

__global__ void zero_kernel(float* __restrict__ p, int n) {
    int i = blockIdx.x * blockDim.x + threadIdx.x;
    if (i < n) p[i] = 0.f;
}

// ======================= big GEMM (mma.sync bf16, split-3, 3-stage) =======================
#define SA_HI 0
#define SA_LO 16384
#define SB_HI 32768
#define SB_LO 49152
#define STAGE 65536

__global__ __launch_bounds__(256, 1)
void gemm_tc_kernel(const __nv_bfloat16* __restrict__ Ahi, const __nv_bfloat16* __restrict__ Alo,
                    const __nv_bfloat16* __restrict__ Bhi, const __nv_bfloat16* __restrict__ Blo,
                    const float* __restrict__ bias, float* __restrict__ Cf,
                    __nv_bfloat16* __restrict__ Chi, __nv_bfloat16* __restrict__ Clo, int mode) {
    extern __shared__ char smem[];
    uint32_t sb = smem_u32(smem);
    int tid = threadIdx.x, wid = tid >> 5, lane = tid & 31;
    int row0 = blockIdx.y * 128, col0 = blockIdx.x * 128;
    int wm = (wid & 1) * 64, wn = (wid >> 1) * 32;

    float acc[4][4][4];
    #pragma unroll
    for (int a = 0; a < 4; a++)
        #pragma unroll
        for (int bq = 0; bq < 4; bq++)
            #pragma unroll
            for (int cq = 0; cq < 4; cq++) acc[a][bq][cq] = 0.f;

    // prologue: stages 0, 1
    #pragma unroll
    for (int p = 0; p < 2; p++) {
        uint32_t s0 = sb + p * STAGE;
        int kc = p * 64;
        cp_tile64(Ahi, row0, HH, kc, s0 + SA_HI, tid, 128);
        cp_tile64(Alo, row0, HH, kc, s0 + SA_LO, tid, 128);
        cp_tile64(Bhi, col0, HH, kc, s0 + SB_HI, tid, 128);
        cp_tile64(Blo, col0, HH, kc, s0 + SB_LO, tid, 128);
        CP_COMMIT();
    }

    for (int c = 0; c < 12; c++) {
        int buf = c % 3;
        if (c + 2 < 12) {
            uint32_t sn = sb + ((c + 2) % 3) * STAGE;
            int kc = (c + 2) * 64;
            cp_tile64(Ahi, row0, HH, kc, sn + SA_HI, tid, 128);
            cp_tile64(Alo, row0, HH, kc, sn + SA_LO, tid, 128);
            cp_tile64(Bhi, col0, HH, kc, sn + SB_HI, tid, 128);
            cp_tile64(Blo, col0, HH, kc, sn + SB_LO, tid, 128);
            CP_COMMIT();
            CP_WAIT2();
        } else if (c + 1 < 12) {
            CP_WAIT1();
        } else {
            CP_WAIT0();
        }
        __syncthreads();

        uint32_t s0 = sb + buf * STAGE;
        #pragma unroll
        for (int ks = 0; ks < 4; ks++) {
            uint32_t bh2[2][4], bl2[2][4];
            #pragma unroll
            for (int half = 0; half < 2; half++) {
                int nr = wn + half * 16 + (lane & 7) + ((lane & 16) ? 8 : 0);
                int kb = ks * 32 + ((lane & 8) ? 16 : 0);
                ldsm4(bh2[half], s0 + SB_HI + SWZ((uint32_t)(nr * 128 + kb)));
                ldsm4(bl2[half], s0 + SB_LO + SWZ((uint32_t)(nr * 128 + kb)));
            }
            #pragma unroll
            for (int im = 0; im < 4; im++) {
                int rowa = wm + im * 16 + (lane & 15);
                int ka = ks * 32 + ((lane & 16) ? 16 : 0);
                uint32_t ah[4], al[4];
                ldsm4(ah, s0 + SA_HI + SWZ((uint32_t)(rowa * 128 + ka)));
                ldsm4(al, s0 + SA_LO + SWZ((uint32_t)(rowa * 128 + ka)));
                #pragma unroll
                for (int in = 0; in < 4; in++) {
                    const uint32_t* bhp = &bh2[in >> 1][(in & 1) * 2];
                    const uint32_t* blp = &bl2[in >> 1][(in & 1) * 2];
                    mma16816(acc[im][in], ah, bhp);
                    mma16816(acc[im][in], al, bhp);
                    mma16816(acc[im][in], ah, blp);
                }
            }
        }
        __syncthreads();
    }

    // stage accumulators to smem
    float* fs = reinterpret_cast<float*>(smem);
    #pragma unroll
    for (int im = 0; im < 4; im++)
        #pragma unroll
        for (int in = 0; in < 4; in++) {
            int r = wm + im * 16 + (lane >> 2);
            int cc = wn + in * 8 + (lane & 3) * 2;
            fs[r * 132 + cc]           = acc[im][in][0];
            fs[r * 132 + cc + 1]       = acc[im][in][1];
            fs[(r + 8) * 132 + cc]     = acc[im][in][2];
            fs[(r + 8) * 132 + cc + 1] = acc[im][in][3];
        }
    __syncthreads();

    if (mode <= 1) {
        for (int i = tid; i < 128 * 128; i += 256) {
            int r = i >> 7, cc = i & 127;
            float v = fs[r * 132 + cc] + bias[col0 + cc];
            size_t o = (size_t)(row0 + r) * HH + col0 + cc;
            if (mode == 0) Cf[o] = v;
            else { __nv_bfloat16 h, l; split2(v, h, l); Chi[o] = h; Clo[o] = l; }
        }
    } else {
        int r = tid >> 1, g = tid & 1;
        int cb = g * 64;
        float mx = -1e30f;
        #pragma unroll
        for (int m = 0; m < 64; m++)
            mx = fmaxf(mx, fs[r * 132 + cb + m] + bias[col0 + cb + m]);
        int tok = row0 + r;
        if (mode == 2) {
            size_t ob = (size_t)tok * HH + col0 + cb;
            for (int m = 0; m < 64; m++) {
                float e = __expf(fs[r * 132 + cb + m] + bias[col0 + cb + m] - mx);
                __nv_bfloat16 h, l; split2(e, h, l);
                Chi[ob + m] = h; Clo[ob + m] = l;
            }
        } else {
            int b = tok >> 13, s = tok & (SS - 1);
            int h = (col0 + cb) >> 6;
            size_t ob = ((size_t)(b * NH + h) * SS + s) * MM;
            for (int m = 0; m < 64; m++)
                Cf[ob + m] = __expf(fs[r * 132 + cb + m] + bias[col0 + cb + m] - mx);
        }
    }
}

// ======================= qkv GEMM + normalize (N=80) =======================
// A = qp hi/lo [tok][768] at col h*64 (K=64). B = kvx [bh][80][64].
__global__ __launch_bounds__(256, 1)
void qkv_tc_kernel(const __nv_bfloat16* __restrict__ QPhi, const __nv_bfloat16* __restrict__ QPlo,
                   const __nv_bfloat16* __restrict__ KVhi, const __nv_bfloat16* __restrict__ KVlo,
                   __nv_bfloat16* __restrict__ Chi, __nv_bfloat16* __restrict__ Clo) {
    extern __shared__ char smem[];
    uint32_t sb = smem_u32(smem);
    int tid = threadIdx.x, wid = tid >> 5, lane = tid & 31;
    int bh = blockIdx.y, b = bh / NH, h = bh % NH;
    int s0 = blockIdx.x * 128;
    int row0 = b * SS + s0;
    int wm = (wid >> 1) * 32;          // 4 m-groups of 32
    int wn = (wid & 1) * 32;           // 2 n-groups of 32
    int has_x = (wid & 1);             // n-group 1 also owns cols 64-79

    cp_tile64(QPhi + h * 64, row0, HH, 0, sb + SA_HI, tid, 128);
    cp_tile64(QPlo + h * 64, row0, HH, 0, sb + SA_LO, tid, 128);
    cp_tile64(KVhi + (size_t)bh * 128 * 64, 0, 64, 0, sb + SB_HI, tid, 80);
    cp_tile64(KVlo + (size_t)bh * 128 * 64, 0, 64, 0, sb + SB_LO, tid, 80);
    CP_COMMIT();
    CP_WAIT0();
    __syncthreads();

    float acc[2][4][4];
    float accx[2][4];
    #pragma unroll
    for (int a = 0; a < 2; a++) {
        #pragma unroll
        for (int bq = 0; bq < 4; bq++)
            #pragma unroll
            for (int cq = 0; cq < 4; cq++) acc[a][bq][cq] = 0.f;
        #pragma unroll
        for (int cq = 0; cq < 4; cq++) accx[a][cq] = 0.f;
    }

    #pragma unroll
    for (int ks = 0; ks < 4; ks++) {
        uint32_t bh2[2][4], bl2[2][4], bxh[4], bxl[4];
        int kb = ks * 32 + ((lane & 8) ? 16 : 0);
        #pragma unroll
        for (int half = 0; half < 2; half++) {
            int nr = wn + half * 16 + (lane & 7) + ((lane & 16) ? 8 : 0);
            ldsm4(bh2[half], sb + SB_HI + SWZ((uint32_t)(nr * 128 + kb)));
            ldsm4(bl2[half], sb + SB_LO + SWZ((uint32_t)(nr * 128 + kb)));
        }
        if (has_x) {
            int nr = 64 + (lane & 7) + ((lane & 16) ? 8 : 0);
            ldsm4(bxh, sb + SB_HI + SWZ((uint32_t)(nr * 128 + kb)));
            ldsm4(bxl, sb + SB_LO + SWZ((uint32_t)(nr * 128 + kb)));
        }
        #pragma unroll
        for (int im = 0; im < 2; im++) {
            int rowa = wm + im * 16 + (lane & 15);
            int ka = ks * 32 + ((lane & 16) ? 16 : 0);
            uint32_t ah[4], al[4];
            ldsm4(ah, sb + SA_HI + SWZ((uint32_t)(rowa * 128 + ka)));
            ldsm4(al, sb + SA_LO + SWZ((uint32_t)(rowa * 128 + ka)));
            #pragma unroll
            for (int in = 0; in < 4; in++) {
                const uint32_t* bhp = &bh2[in >> 1][(in & 1) * 2];
                const uint32_t* blp = &bl2[in >> 1][(in & 1) * 2];
                mma16816(acc[im][in], ah, bhp);
                mma16816(acc[im][in], al, bhp);
                mma16816(acc[im][in], ah, blp);
            }
            if (has_x) {
                mma16816(accx[im], ah, &bxh[0]);
                mma16816(accx[im], al, &bxh[0]);
                mma16816(accx[im], ah, &bxl[0]);
            }
        }
    }
    __syncthreads();

    float* fs = reinterpret_cast<float*>(smem);
    #pragma unroll
    for (int im = 0; im < 2; im++) {
        int r = wm + im * 16 + (lane >> 2);
        #pragma unroll
        for (int in = 0; in < 4; in++) {
            int cc = wn + in * 8 + (lane & 3) * 2;
            fs[r * 84 + cc]           = acc[im][in][0];
            fs[r * 84 + cc + 1]       = acc[im][in][1];
            fs[(r + 8) * 84 + cc]     = acc[im][in][2];
            fs[(r + 8) * 84 + cc + 1] = acc[im][in][3];
        }
        if (has_x) {
            int cc = 64 + (lane & 3) * 2;
            fs[r * 84 + cc]           = accx[im][0];
            fs[r * 84 + cc + 1]       = accx[im][1];
            fs[(r + 8) * 84 + cc]     = accx[im][2];
            fs[(r + 8) * 84 + cc + 1] = accx[im][3];
        }
    }
    __syncthreads();

    for (int i = tid; i < 128 * 64; i += 256) {
        int r = i >> 6, d = i & 63;
        float inv = 1.0f / (fs[r * 84 + 64] + EPSF);
        float v = fs[r * 84 + d] * inv;
        __nv_bfloat16 hh, ll; split2(v, hh, ll);
        size_t o = (size_t)(row0 + r) * HH + h * HD + d;
        Chi[o] = hh; Clo[o] = ll;
    }
}

// ======================= kv summary (SIMT, float4-vectorized) =======================
#define KV_SPLITS 32
#define KV_ROWS (SS / KV_SPLITS)   // 256
#define KV_CH 32

__global__ __launch_bounds__(256)
void kv_accum_kernel(const float* __restrict__ kp,   // [BHS, SS, MM]
                     const float* __restrict__ v,    // [NTOK, HH]
                     float* __restrict__ kv,         // [BHS, MM, HD]
                     float* __restrict__ ksum) {     // [BHS, MM]
    int bh = blockIdx.y;
    int b = bh / NH, h = bh % NH;
    int split = blockIdx.x;
    int tid = threadIdx.x;
    int m = tid & 63;
    int dg = tid >> 6;               // 0..3

    __shared__ float4 kps4[KV_CH][16];
    __shared__ float4 vs4[KV_CH][16];

    float acc[16] = {};
    float ks = 0.f;
    int n0 = split * KV_ROWS;

    for (int c0 = 0; c0 < KV_ROWS; c0 += KV_CH) {
        #pragma unroll
        for (int i = tid; i < KV_CH * 16; i += 256) {
            int r = i >> 4, c4 = i & 15;
            int n = n0 + c0 + r;
            kps4[r][c4] = *reinterpret_cast<const float4*>(kp + ((size_t)bh * SS + n) * MM + c4 * 4);
            vs4[r][c4]  = *reinterpret_cast<const float4*>(v + ((size_t)(b * SS + n)) * HH + h * HD + c4 * 4);
        }
        __syncthreads();
        #pragma unroll
        for (int r = 0; r < KV_CH; r++) {
            float a = reinterpret_cast<const float*>(&kps4[r][0])[m];
            if (dg == 0) ks += a;
            #pragma unroll
            for (int j4 = 0; j4 < 4; j4++) {
                float4 vv = vs4[r][dg * 4 + j4];
                acc[j4 * 4 + 0] = fmaf(a, vv.x, acc[j4 * 4 + 0]);
                acc[j4 * 4 + 1] = fmaf(a, vv.y, acc[j4 * 4 + 1]);
                acc[j4 * 4 + 2] = fmaf(a, vv.z, acc[j4 * 4 + 2]);
                acc[j4 * 4 + 3] = fmaf(a, vv.w, acc[j4 * 4 + 3]);
            }
        }
        __syncthreads();
    }

    float* kvp = kv + ((size_t)bh * MM + m) * HD + dg * 16;
    #pragma unroll
    for (int j = 0; j < 16; j++) atomicAdd(&kvp[j], acc[j]);
    if (dg == 0) atomicAdd(&ksum[(size_t)bh * MM + m], ks);
}

// ======================= launch =======================
extern "C" void kernel_launch(void* const* d_in, const int* in_sizes, int n_in,
                              void* d_out, int out_size) {
    const float* X  = (const float*)d_in[0];
    const float* Wq = (const float*)d_in[1];
    const float* bq = (const float*)d_in[2];
    const float* Wk = (const float*)d_in[3];
    const float* bk = (const float*)d_in[4];
    const float* Wv = (const float*)d_in[5];
    const float* bv = (const float*)d_in[6];
    const float* Wo = (const float*)d_in[7];
    const float* bo = (const float*)d_in[8];
    const float* P  = (const float*)d_in[9];
    float* out = (float*)d_out;

    __nv_bfloat16 *xhi, *xlo, *wqph, *wqpl, *wkph, *wkpl, *wvth, *wvtl, *woth, *wotl;
    __nv_bfloat16 *qphi, *qplo, *kvxh, *kvxl, *ctxh, *ctxl;
    float *bqf, *bkf, *vf, *kpf, *kvf, *ksum;
    cudaGetSymbolAddress((void**)&xhi, g_xhi);   cudaGetSymbolAddress((void**)&xlo, g_xlo);
    cudaGetSymbolAddress((void**)&wqph, g_wqph); cudaGetSymbolAddress((void**)&wqpl, g_wqpl);
    cudaGetSymbolAddress((void**)&wkph, g_wkph); cudaGetSymbolAddress((void**)&wkpl, g_wkpl);
    cudaGetSymbolAddress((void**)&wvth, g_wvth); cudaGetSymbolAddress((void**)&wvtl, g_wvtl);
    cudaGetSymbolAddress((void**)&woth, g_woth); cudaGetSymbolAddress((void**)&wotl, g_wotl);
    cudaGetSymbolAddress((void**)&bqf, g_bqf);   cudaGetSymbolAddress((void**)&bkf, g_bkf);
    cudaGetSymbolAddress((void**)&qphi, g_qphi); cudaGetSymbolAddress((void**)&qplo, g_qplo);
    cudaGetSymbolAddress((void**)&kpf, g_kpf);   cudaGetSymbolAddress((void**)&vf, g_v);
    cudaGetSymbolAddress((void**)&kvf, g_kv);    cudaGetSymbolAddress((void**)&ksum, g_ksum);
    cudaGetSymbolAddress((void**)&kvxh, g_kvxh); cudaGetSymbolAddress((void**)&kvxl, g_kvxl);
    cudaGetSymbolAddress((void**)&ctxh, g_ctxh); cudaGetSymbolAddress((void**)&ctxl, g_ctxl);

    cudaFuncSetAttribute(gemm_tc_kernel, cudaFuncAttributeMaxDynamicSharedMemorySize, 196608);
    cudaFuncSetAttribute(qkv_tc_kernel,  cudaFuncAttributeMaxDynamicSharedMemorySize, 69632);

    // preprocessing (5 launches -> launch #5 is the first big GEMM for ncu -s 5 -c 1)
    split_f32_kernel<<<2048, 256>>>(X, xhi, xlo, (size_t)NTOK * HH / 2);         // 0
    dim3 wtg(HH / 32, HH / 32, 2);
    wt_prep_kernel<<<wtg, dim3(32, 8)>>>(Wv, Wo, wvth, wvtl, woth, wotl);        // 1
    dim3 fwg(HH / 64, NH);
    fold_w_kernel<<<fwg, 256>>>(Wq, P, wqph, wqpl);                              // 2
    fold_w_kernel<<<fwg, 256>>>(Wk, P, wkph, wkpl);                              // 3
    fold_b_kernel<<<dim3(NH, 2), 64>>>(bq, bk, P, bqf, bkf);                     // 4

    dim3 gg(HH / 128, NTOK / 128);    // (6, 256)
    // qp = exp(X@Wqp + bqf - rowmax)  (split bf16, [tok][768])     <- ncu captures this
    gemm_tc_kernel<<<gg, 256, 196608>>>(xhi, xlo, wqph, wqpl, bqf, nullptr, qphi, qplo, 2);
    // kp = exp(X@Wkp + bkf - rowmax)  (fp32, [bh][s][64])
    gemm_tc_kernel<<<gg, 256, 196608>>>(xhi, xlo, wkph, wkpl, bkf, kpf, nullptr, nullptr, 3);
    // v = X@Wv + bv  (fp32)
    gemm_tc_kernel<<<gg, 256, 196608>>>(xhi, xlo, wvth, wvtl, bv, vf, nullptr, nullptr, 0);

    // kv summary
    zero_kernel<<<(BHS * MM * HD + 255) / 256, 256>>>(kvf, BHS * MM * HD);
    zero_kernel<<<(BHS * MM + 255) / 256, 256>>>(ksum, BHS * MM);
    dim3 kvg(KV_SPLITS, BHS);
    kv_accum_kernel<<<kvg, 256>>>(kpf, vf, kvf, ksum);
    kvx_prep_kernel<<<BHS, 256>>>(kvf, ksum, kvxh, kvxl);

    // recombine + normalize -> ctx split bf16
    dim3 pg(SS / 128, BHS);           // (64, 48)
    qkv_tc_kernel<<<pg, 256, 69632>>>(qphi, qplo, kvxh, kvxl, ctxh, ctxl);

    // out = ctx@Wo + bo (fp32)
    gemm_tc_kernel<<<gg, 256, 196608>>>(ctxh, ctxl, woth, wotl, bo, out, nullptr, nullptr, 0);
}